// round 3
// baseline (speedup 1.0000x reference)
#include <cuda_runtime.h>
#include <math.h>

#define LL 2048
#define EDGE_DIM 32
#define NODE_DIM 64
#define NTHREADS 256
#define JPT (LL / NTHREADS)   // 8 j's per thread

__device__ __forceinline__ void combine_state(
    float& m, float& s, float& vx, float& vy, float& vz,
    float m2, float s2, float x2, float y2, float z2)
{
    float M  = fmaxf(m, m2);
    float c1 = __expf(m  - M);   // exp(0)=1 when m is the max
    float c2 = __expf(m2 - M);
    s  = s  * c1 + s2 * c2;
    vx = vx * c1 + x2 * c2;
    vy = vy * c1 + y2 * c2;
    vz = vz * c1 + z2 * c2;
    m  = M;
}

__global__ __launch_bounds__(NTHREADS)
void se3_equiv_kernel(const float* __restrict__ coords,
                      const float* __restrict__ nodef,
                      const float* __restrict__ pairf,
                      const float* __restrict__ w_attn,
                      const float* __restrict__ w_mag,
                      const float* __restrict__ b_mag,
                      float* __restrict__ out)
{
    __shared__ float sc[LL * 3];          // all coords, 24 KB
    __shared__ float red[8][5];           // per-warp partial states

    const int tid = threadIdx.x;
    const int i   = blockIdx.x;
    const int lane = tid & 31;
    const int warp = tid >> 5;

    // stage coords into shared
    for (int idx = tid; idx < 3 * LL; idx += NTHREADS) sc[idx] = coords[idx];

    // w_attn[0:33] into registers via scalar loads (alignment-agnostic)
    float w[EDGE_DIM];
    #pragma unroll
    for (int c = 0; c < EDGE_DIM; ++c) w[c] = __ldg(&w_attn[c]);
    const float wd = __ldg(&w_attn[EDGE_DIM]);
    __syncthreads();

    const float cix = sc[3*i+0], ciy = sc[3*i+1], ciz = sc[3*i+2];

    // online softmax state
    const float NEG_INF = -3.402823466e38f;
    float m = NEG_INF, s = 0.f, vx = 0.f, vy = 0.f, vz = 0.f;

    const float4* pf = reinterpret_cast<const float4*>(
        pairf + (size_t)i * LL * EDGE_DIM);

    #pragma unroll 2
    for (int k = 0; k < JPT; ++k) {
        const int j = tid + k * NTHREADS;
        const float4* p = pf + (size_t)j * (EDGE_DIM / 4);

        // 32-wide dot with w_attn
        float4 t0 = p[0], t1 = p[1], t2 = p[2], t3 = p[3];
        float4 t4 = p[4], t5 = p[5], t6 = p[6], t7 = p[7];
        float dot = t0.x * w[0];
        dot = fmaf(t0.y, w[1],  dot); dot = fmaf(t0.z, w[2],  dot); dot = fmaf(t0.w, w[3],  dot);
        dot = fmaf(t1.x, w[4],  dot); dot = fmaf(t1.y, w[5],  dot); dot = fmaf(t1.z, w[6],  dot); dot = fmaf(t1.w, w[7],  dot);
        dot = fmaf(t2.x, w[8],  dot); dot = fmaf(t2.y, w[9],  dot); dot = fmaf(t2.z, w[10], dot); dot = fmaf(t2.w, w[11], dot);
        dot = fmaf(t3.x, w[12], dot); dot = fmaf(t3.y, w[13], dot); dot = fmaf(t3.z, w[14], dot); dot = fmaf(t3.w, w[15], dot);
        dot = fmaf(t4.x, w[16], dot); dot = fmaf(t4.y, w[17], dot); dot = fmaf(t4.z, w[18], dot); dot = fmaf(t4.w, w[19], dot);
        dot = fmaf(t5.x, w[20], dot); dot = fmaf(t5.y, w[21], dot); dot = fmaf(t5.z, w[22], dot); dot = fmaf(t5.w, w[23], dot);
        dot = fmaf(t6.x, w[24], dot); dot = fmaf(t6.y, w[25], dot); dot = fmaf(t6.z, w[26], dot); dot = fmaf(t6.w, w[27], dot);
        dot = fmaf(t7.x, w[28], dot); dot = fmaf(t7.y, w[29], dot); dot = fmaf(t7.z, w[30], dot); dot = fmaf(t7.w, w[31], dot);

        // geometry
        const float dx = cix - sc[3*j+0];
        const float dy = ciy - sc[3*j+1];
        const float dz = ciz - sc[3*j+2];
        const float d2 = fmaf(dx, dx, fmaf(dy, dy, dz * dz));
        const float r  = rsqrtf(d2 + 1e-30f);   // diagonal (d2=0): r finite, dir->0
        const float d  = d2 * r;                // sqrt(d2)
        const float logit = fmaf(d, wd, dot);   // b_attn cancels in softmax

        // online softmax update, single exp: exp(min - max); other factor is 1
        const float M  = fmaxf(m, logit);
        const float z  = __expf(fminf(m, logit) - M);
        const bool  gt = (logit > m);
        const float c1 = gt ? z   : 1.f;   // scale on old state
        const float e  = gt ? 1.f : z;     // weight of new element
        m  = M;
        s  = fmaf(s, c1, e);
        const float er = e * r;
        vx = fmaf(vx, c1, er * dx);
        vy = fmaf(vy, c1, er * dy);
        vz = fmaf(vz, c1, er * dz);
    }

    // intra-warp tree combine
    #pragma unroll
    for (int o = 16; o > 0; o >>= 1) {
        float m2 = __shfl_xor_sync(0xFFFFFFFFu, m,  o);
        float s2 = __shfl_xor_sync(0xFFFFFFFFu, s,  o);
        float x2 = __shfl_xor_sync(0xFFFFFFFFu, vx, o);
        float y2 = __shfl_xor_sync(0xFFFFFFFFu, vy, o);
        float z2 = __shfl_xor_sync(0xFFFFFFFFu, vz, o);
        combine_state(m, s, vx, vy, vz, m2, s2, x2, y2, z2);
    }
    if (lane == 0) {
        red[warp][0] = m;  red[warp][1] = s;
        red[warp][2] = vx; red[warp][3] = vy; red[warp][4] = vz;
    }
    __syncthreads();

    if (warp == 0) {
        // load 8 warp partials into lanes 0..7; neutral elsewhere
        if (lane < 8) {
            m  = red[lane][0]; s  = red[lane][1];
            vx = red[lane][2]; vy = red[lane][3]; vz = red[lane][4];
        } else {
            m = NEG_INF; s = 0.f; vx = 0.f; vy = 0.f; vz = 0.f;
        }
        #pragma unroll
        for (int o = 4; o > 0; o >>= 1) {
            float m2 = __shfl_xor_sync(0xFFFFFFFFu, m,  o);
            float s2 = __shfl_xor_sync(0xFFFFFFFFu, s,  o);
            float x2 = __shfl_xor_sync(0xFFFFFFFFu, vx, o);
            float y2 = __shfl_xor_sync(0xFFFFFFFFu, vy, o);
            float z2 = __shfl_xor_sync(0xFFFFFFFFu, vz, o);
            combine_state(m, s, vx, vy, vz, m2, s2, x2, y2, z2);
        }

        // magnitude: tanh(node_features[i] @ w_mag + b_mag) * 0.1
        float a = fmaf(nodef[(size_t)i * NODE_DIM + lane],      __ldg(&w_mag[lane]),
                  nodef[(size_t)i * NODE_DIM + 32 + lane] * __ldg(&w_mag[32 + lane]));
        #pragma unroll
        for (int o = 16; o > 0; o >>= 1) a += __shfl_xor_sync(0xFFFFFFFFu, a, o);

        if (lane == 0) {
            const float mag  = tanhf(a + __ldg(&b_mag[0])) * 0.1f;
            const float invs = 1.f / s;
            const float fac  = invs * mag;
            out[3*i+0] = cix + vx * fac;
            out[3*i+1] = ciy + vy * fac;
            out[3*i+2] = ciz + vz * fac;
        }
    }
}

extern "C" void kernel_launch(void* const* d_in, const int* in_sizes, int n_in,
                              void* d_out, int out_size)
{
    const float* coords = (const float*)d_in[0];
    const float* nodef  = (const float*)d_in[1];
    const float* pairf  = (const float*)d_in[2];
    const float* w_attn = (const float*)d_in[3];
    // d_in[4] = b_attn : softmax-invariant, unused
    const float* w_mag  = (const float*)d_in[5];
    const float* b_mag  = (const float*)d_in[6];
    float* out = (float*)d_out;

    se3_equiv_kernel<<<LL, NTHREADS>>>(coords, nodef, pairf, w_attn, w_mag, b_mag, out);
}

// round 4
// speedup vs baseline: 1.4220x; 1.4220x over previous
#include <cuda_runtime.h>
#include <math.h>

#define LL 2048
#define EDGE_DIM 32
#define NODE_DIM 64
#define NTHREADS 256
#define NWARPS (NTHREADS / 32)
#define JPW (LL / NWARPS)        // 256 j's per warp
#define NSTEPS (JPW / 4)         // 64 steps, 4 rows per warp-step

__device__ __forceinline__ void combine_state(
    float& m, float& s, float& vx, float& vy, float& vz,
    float m2, float s2, float x2, float y2, float z2)
{
    float M  = fmaxf(m, m2);
    float c1 = __expf(m  - M);
    float c2 = __expf(m2 - M);
    s  = s  * c1 + s2 * c2;
    vx = vx * c1 + x2 * c2;
    vy = vy * c1 + y2 * c2;
    vz = vz * c1 + z2 * c2;
    m  = M;
}

__global__ __launch_bounds__(NTHREADS)
void se3_equiv_kernel(const float* __restrict__ coords,
                      const float* __restrict__ nodef,
                      const float* __restrict__ pairf,
                      const float* __restrict__ w_attn,
                      const float* __restrict__ w_mag,
                      const float* __restrict__ b_mag,
                      float* __restrict__ out)
{
    __shared__ float sc[LL * 3];          // all coords, 24 KB
    __shared__ float red[NWARPS][5];      // per-warp partial states

    const int tid  = threadIdx.x;
    const int i    = blockIdx.x;
    const int lane = tid & 31;
    const int warp = tid >> 5;
    const int grp  = lane >> 3;           // 4 row-groups of 8 lanes

    // stage coords into shared
    for (int idx = tid; idx < 3 * LL; idx += NTHREADS) sc[idx] = coords[idx];

    // this lane's 4 attention weights: w_attn[4*(lane&7) .. +3]
    const int wbase = (lane & 7) * 4;
    const float w0 = __ldg(&w_attn[wbase + 0]);
    const float w1 = __ldg(&w_attn[wbase + 1]);
    const float w2 = __ldg(&w_attn[wbase + 2]);
    const float w3 = __ldg(&w_attn[wbase + 3]);
    const float wd = __ldg(&w_attn[EDGE_DIM]);
    __syncthreads();

    const float cix = sc[3*i+0], ciy = sc[3*i+1], ciz = sc[3*i+2];

    const float NEG_INF = -3.402823466e38f;
    float m = NEG_INF, s = 0.f, vx = 0.f, vy = 0.f, vz = 0.f;

    // row i's pair features as float4; warp-step base advances 4 rows (32 float4)
    const float4* pf4 = reinterpret_cast<const float4*>(
        pairf + (size_t)i * LL * EDGE_DIM);
    const int jw = warp * JPW;            // this warp's first row

    #pragma unroll 4
    for (int k = 0; k < NSTEPS; ++k) {
        // fully coalesced: 32 lanes cover 4 consecutive rows (512 B contiguous)
        const float4 t = pf4[(size_t)(jw + 4*k) * 8 + lane];

        // partial dot (4 elems), then sum across the 8-lane group
        float dot = t.x * w0;
        dot = fmaf(t.y, w1, dot);
        dot = fmaf(t.z, w2, dot);
        dot = fmaf(t.w, w3, dot);
        dot += __shfl_xor_sync(0xFFFFFFFFu, dot, 1);
        dot += __shfl_xor_sync(0xFFFFFFFFu, dot, 2);
        dot += __shfl_xor_sync(0xFFFFFFFFu, dot, 4);
        // all 8 lanes of a group now hold the full 32-wide dot for row j

        const int j = jw + 4*k + grp;

        // geometry (broadcast reads from smem; 4 distinct j per warp)
        const float dx = cix - sc[3*j+0];
        const float dy = ciy - sc[3*j+1];
        const float dz = ciz - sc[3*j+2];
        const float d2 = fmaf(dx, dx, fmaf(dy, dy, dz * dz));
        const float r  = rsqrtf(d2 + 1e-30f);   // diagonal: dir -> 0
        const float d  = d2 * r;                // sqrt(d2)
        const float logit = fmaf(d, wd, dot);   // b_attn cancels in softmax

        // online softmax update (single exp); redundant across the 8-lane group
        const float M  = fmaxf(m, logit);
        const float z  = __expf(fminf(m, logit) - M);
        const bool  gt = (logit > m);
        const float c1 = gt ? z   : 1.f;
        const float e  = gt ? 1.f : z;
        m  = M;
        s  = fmaf(s, c1, e);
        const float er = e * r;
        vx = fmaf(vx, c1, er * dx);
        vy = fmaf(vy, c1, er * dy);
        vz = fmaf(vz, c1, er * dz);
    }

    // combine the 4 groups (lanes within a group hold identical state)
    #pragma unroll
    for (int o = 8; o <= 16; o <<= 1) {
        float m2 = __shfl_xor_sync(0xFFFFFFFFu, m,  o);
        float s2 = __shfl_xor_sync(0xFFFFFFFFu, s,  o);
        float x2 = __shfl_xor_sync(0xFFFFFFFFu, vx, o);
        float y2 = __shfl_xor_sync(0xFFFFFFFFu, vy, o);
        float z2 = __shfl_xor_sync(0xFFFFFFFFu, vz, o);
        combine_state(m, s, vx, vy, vz, m2, s2, x2, y2, z2);
    }
    if (lane == 0) {
        red[warp][0] = m;  red[warp][1] = s;
        red[warp][2] = vx; red[warp][3] = vy; red[warp][4] = vz;
    }
    __syncthreads();

    if (warp == 0) {
        if (lane < NWARPS) {
            m  = red[lane][0]; s  = red[lane][1];
            vx = red[lane][2]; vy = red[lane][3]; vz = red[lane][4];
        } else {
            m = NEG_INF; s = 0.f; vx = 0.f; vy = 0.f; vz = 0.f;
        }
        #pragma unroll
        for (int o = 4; o > 0; o >>= 1) {
            float m2 = __shfl_xor_sync(0xFFFFFFFFu, m,  o);
            float s2 = __shfl_xor_sync(0xFFFFFFFFu, s,  o);
            float x2 = __shfl_xor_sync(0xFFFFFFFFu, vx, o);
            float y2 = __shfl_xor_sync(0xFFFFFFFFu, vy, o);
            float z2 = __shfl_xor_sync(0xFFFFFFFFu, vz, o);
            combine_state(m, s, vx, vy, vz, m2, s2, x2, y2, z2);
        }

        // magnitude: tanh(node_features[i] @ w_mag + b_mag) * 0.1
        float a = fmaf(nodef[(size_t)i * NODE_DIM + lane],      __ldg(&w_mag[lane]),
                  nodef[(size_t)i * NODE_DIM + 32 + lane] * __ldg(&w_mag[32 + lane]));
        #pragma unroll
        for (int o = 16; o > 0; o >>= 1) a += __shfl_xor_sync(0xFFFFFFFFu, a, o);

        if (lane == 0) {
            const float mag = tanhf(a + __ldg(&b_mag[0])) * 0.1f;
            const float fac = mag / s;
            out[3*i+0] = cix + vx * fac;
            out[3*i+1] = ciy + vy * fac;
            out[3*i+2] = ciz + vz * fac;
        }
    }
}

extern "C" void kernel_launch(void* const* d_in, const int* in_sizes, int n_in,
                              void* d_out, int out_size)
{
    const float* coords = (const float*)d_in[0];
    const float* nodef  = (const float*)d_in[1];
    const float* pairf  = (const float*)d_in[2];
    const float* w_attn = (const float*)d_in[3];
    // d_in[4] = b_attn : softmax-invariant, unused
    const float* w_mag  = (const float*)d_in[5];
    const float* b_mag  = (const float*)d_in[6];
    float* out = (float*)d_out;

    se3_equiv_kernel<<<LL, NTHREADS>>>(coords, nodef, pairf, w_attn, w_mag, b_mag, out);
}

// round 5
// speedup vs baseline: 1.4445x; 1.0158x over previous
#include <cuda_runtime.h>
#include <math.h>

#define LL 2048
#define EDGE_DIM 32
#define NODE_DIM 64
#define NTHREADS 256
#define NWARPS (NTHREADS / 32)
#define JPW (LL / NWARPS)        // 256 j's per warp
#define NSTEPS (JPW / 4)         // 64 steps, 4 rows per warp-step

#define LOG2E 1.4426950408889634f
#define LANE_SHIFT (-4.0f)       // x8 lanes => -32 in log2 units (softmax-invariant)

__device__ __forceinline__ float ex2f(float x) {
    float y;
    asm("ex2.approx.f32 %0, %1;" : "=f"(y) : "f"(x));
    return y;
}

__global__ __launch_bounds__(NTHREADS)
void se3_equiv_kernel(const float* __restrict__ coords,
                      const float* __restrict__ nodef,
                      const float* __restrict__ pairf,
                      const float* __restrict__ w_attn,
                      const float* __restrict__ w_mag,
                      const float* __restrict__ b_mag,
                      float* __restrict__ out)
{
    __shared__ float4 ud[LL];            // {ux, uy, uz, d} per j, 32 KB
    __shared__ float  red[NWARPS][4];    // per-warp partial sums

    const int tid  = threadIdx.x;
    const int i    = blockIdx.x;
    const int lane = tid & 31;
    const int warp = tid >> 5;
    const int grp  = lane >> 3;          // 4 row-groups of 8 lanes

    // this lane's 4 attention weights, pre-scaled by log2(e)
    const int wbase = (lane & 7) * 4;
    const float w0  = __ldg(&w_attn[wbase + 0]) * LOG2E;
    const float w1  = __ldg(&w_attn[wbase + 1]) * LOG2E;
    const float w2  = __ldg(&w_attn[wbase + 2]) * LOG2E;
    const float w3  = __ldg(&w_attn[wbase + 3]) * LOG2E;
    const float wdl = __ldg(&w_attn[EDGE_DIM]) * LOG2E;

    const float cix = __ldg(&coords[3*i+0]);
    const float ciy = __ldg(&coords[3*i+1]);
    const float ciz = __ldg(&coords[3*i+2]);

    // precompute unit directions + distances for all j (once per row i)
    for (int j = tid; j < LL; j += NTHREADS) {
        const float dx = cix - __ldg(&coords[3*j+0]);
        const float dy = ciy - __ldg(&coords[3*j+1]);
        const float dz = ciz - __ldg(&coords[3*j+2]);
        const float d2 = fmaf(dx, dx, fmaf(dy, dy, dz * dz));
        const float r  = rsqrtf(d2 + 1e-30f);   // j==i: u->0, d->0
        ud[j] = make_float4(dx * r, dy * r, dz * r, d2 * r);
    }
    __syncthreads();

    float s = 0.f, vx = 0.f, vy = 0.f, vz = 0.f;

    // row i's pair features; 32 lanes cover 4 consecutive rows per step (512 B)
    const float4* pf4 = reinterpret_cast<const float4*>(
        pairf + (size_t)i * LL * EDGE_DIM);
    const int jw = warp * JPW;

    #pragma unroll 8
    for (int k = 0; k < NSTEPS; ++k) {
        const float4 t = pf4[(size_t)(jw + 4*k) * 8 + lane];

        // partial dot (pre-scaled log2 domain) with folded stability shift
        float dot = fmaf(t.x, w0, LANE_SHIFT);
        dot = fmaf(t.y, w1, dot);
        dot = fmaf(t.z, w2, dot);
        dot = fmaf(t.w, w3, dot);
        dot += __shfl_xor_sync(0xFFFFFFFFu, dot, 1);
        dot += __shfl_xor_sync(0xFFFFFFFFu, dot, 2);
        dot += __shfl_xor_sync(0xFFFFFFFFu, dot, 4);
        // all 8 lanes of a group hold the full dot for row j

        const float4 u = ud[jw + 4*k + grp];
        const float  e = ex2f(fmaf(u.w, wdl, dot));   // exp(logit - 22.2)
        s  += e;
        vx  = fmaf(e, u.x, vx);
        vy  = fmaf(e, u.y, vy);
        vz  = fmaf(e, u.z, vz);
    }

    // combine 4 groups (lanes within a group hold identical state): pure sums
    #pragma unroll
    for (int o = 8; o <= 16; o <<= 1) {
        s  += __shfl_xor_sync(0xFFFFFFFFu, s,  o);
        vx += __shfl_xor_sync(0xFFFFFFFFu, vx, o);
        vy += __shfl_xor_sync(0xFFFFFFFFu, vy, o);
        vz += __shfl_xor_sync(0xFFFFFFFFu, vz, o);
    }
    if (lane == 0) {
        red[warp][0] = s;  red[warp][1] = vx;
        red[warp][2] = vy; red[warp][3] = vz;
    }
    __syncthreads();

    if (warp == 0) {
        if (lane < NWARPS) {
            s  = red[lane][0]; vx = red[lane][1];
            vy = red[lane][2]; vz = red[lane][3];
        } else {
            s = 0.f; vx = 0.f; vy = 0.f; vz = 0.f;
        }
        #pragma unroll
        for (int o = 4; o > 0; o >>= 1) {
            s  += __shfl_xor_sync(0xFFFFFFFFu, s,  o);
            vx += __shfl_xor_sync(0xFFFFFFFFu, vx, o);
            vy += __shfl_xor_sync(0xFFFFFFFFu, vy, o);
            vz += __shfl_xor_sync(0xFFFFFFFFu, vz, o);
        }

        // magnitude: tanh(node_features[i] @ w_mag + b_mag) * 0.1
        float a = fmaf(nodef[(size_t)i * NODE_DIM + lane],      __ldg(&w_mag[lane]),
                  nodef[(size_t)i * NODE_DIM + 32 + lane] * __ldg(&w_mag[32 + lane]));
        #pragma unroll
        for (int o = 16; o > 0; o >>= 1) a += __shfl_xor_sync(0xFFFFFFFFu, a, o);

        if (lane == 0) {
            const float mag = tanhf(a + __ldg(&b_mag[0])) * 0.1f;
            const float fac = mag / s;
            out[3*i+0] = cix + vx * fac;
            out[3*i+1] = ciy + vy * fac;
            out[3*i+2] = ciz + vz * fac;
        }
    }
}

extern "C" void kernel_launch(void* const* d_in, const int* in_sizes, int n_in,
                              void* d_out, int out_size)
{
    const float* coords = (const float*)d_in[0];
    const float* nodef  = (const float*)d_in[1];
    const float* pairf  = (const float*)d_in[2];
    const float* w_attn = (const float*)d_in[3];
    // d_in[4] = b_attn : softmax-invariant, unused
    const float* w_mag  = (const float*)d_in[5];
    const float* b_mag  = (const float*)d_in[6];
    float* out = (float*)d_out;

    se3_equiv_kernel<<<LL, NTHREADS>>>(coords, nodef, pairf, w_attn, w_mag, b_mag, out);
}

// round 6
// speedup vs baseline: 1.7227x; 1.1926x over previous
#include <cuda_runtime.h>
#include <math.h>

#define LL 2048
#define EDGE_DIM 32
#define NODE_DIM 64
#define NTHREADS 256
#define NWARPS (NTHREADS / 32)

#define PARTS 4
#define JCHUNK (LL / PARTS)            // 512 j's per CTA
#define JPW (JCHUNK / NWARPS)          // 64 j's per warp
#define NSTEPS (JPW / 4)               // 16 steps, 4 rows per warp-step

#define LOG2E 1.4426950408889634f
#define LANE_SHIFT (-4.0f)             // x8 lanes => -32 in log2 units (softmax-invariant)

__device__ float4 g_part[LL * PARTS];  // per-(row,chunk) partial {s,vx,vy,vz}, 128 KB

__device__ __forceinline__ float ex2f(float x) {
    float y;
    asm("ex2.approx.f32 %0, %1;" : "=f"(y) : "f"(x));
    return y;
}

__global__ __launch_bounds__(NTHREADS)
void se3_main_kernel(const float* __restrict__ coords,
                     const float* __restrict__ pairf,
                     const float* __restrict__ w_attn)
{
    __shared__ float4 ud[JCHUNK];        // {ux,uy,uz,d} for this chunk, 8 KB
    __shared__ float  red[NWARPS][4];

    const int tid  = threadIdx.x;
    const int i    = blockIdx.x;         // row
    const int part = blockIdx.y;         // column chunk
    const int lane = tid & 31;
    const int warp = tid >> 5;
    const int grp  = lane >> 3;          // 4 row-groups of 8 lanes
    const int j0   = part * JCHUNK;

    // this lane's 4 attention weights, pre-scaled by log2(e)
    const int wbase = (lane & 7) * 4;
    const float w0  = __ldg(&w_attn[wbase + 0]) * LOG2E;
    const float w1  = __ldg(&w_attn[wbase + 1]) * LOG2E;
    const float w2  = __ldg(&w_attn[wbase + 2]) * LOG2E;
    const float w3  = __ldg(&w_attn[wbase + 3]) * LOG2E;
    const float wdl = __ldg(&w_attn[EDGE_DIM]) * LOG2E;

    const float cix = __ldg(&coords[3*i+0]);
    const float ciy = __ldg(&coords[3*i+1]);
    const float ciz = __ldg(&coords[3*i+2]);

    // unit directions + distances for this chunk's j's (2 iters/thread)
    for (int jj = tid; jj < JCHUNK; jj += NTHREADS) {
        const int j = j0 + jj;
        const float dx = cix - __ldg(&coords[3*j+0]);
        const float dy = ciy - __ldg(&coords[3*j+1]);
        const float dz = ciz - __ldg(&coords[3*j+2]);
        const float d2 = fmaf(dx, dx, fmaf(dy, dy, dz * dz));
        const float r  = rsqrtf(d2 + 1e-30f);   // j==i: u->0, d->0
        ud[jj] = make_float4(dx * r, dy * r, dz * r, d2 * r);
    }
    __syncthreads();

    float s = 0.f, vx = 0.f, vy = 0.f, vz = 0.f;

    const float4* pf4 = reinterpret_cast<const float4*>(
        pairf + (size_t)i * LL * EDGE_DIM);
    const int jw = j0 + warp * JPW;      // this warp's first row (global j)
    const int lw = warp * JPW;           // local (chunk) index

    #pragma unroll 8
    for (int k = 0; k < NSTEPS; ++k) {
        // coalesced: 32 lanes cover 4 consecutive rows (512 B contiguous)
        const float4 t = pf4[(size_t)(jw + 4*k) * 8 + lane];

        // partial dot (pre-scaled log2 domain) with folded stability shift
        float dot = fmaf(t.x, w0, LANE_SHIFT);
        dot = fmaf(t.y, w1, dot);
        dot = fmaf(t.z, w2, dot);
        dot = fmaf(t.w, w3, dot);
        dot += __shfl_xor_sync(0xFFFFFFFFu, dot, 1);
        dot += __shfl_xor_sync(0xFFFFFFFFu, dot, 2);
        dot += __shfl_xor_sync(0xFFFFFFFFu, dot, 4);
        // all 8 lanes of a group hold the full dot for row j

        const float4 u = ud[lw + 4*k + grp];
        const float  e = ex2f(fmaf(u.w, wdl, dot));
        s  += e;
        vx  = fmaf(e, u.x, vx);
        vy  = fmaf(e, u.y, vy);
        vz  = fmaf(e, u.z, vz);
    }

    // combine 4 groups (lanes within a group hold identical state): pure sums
    #pragma unroll
    for (int o = 8; o <= 16; o <<= 1) {
        s  += __shfl_xor_sync(0xFFFFFFFFu, s,  o);
        vx += __shfl_xor_sync(0xFFFFFFFFu, vx, o);
        vy += __shfl_xor_sync(0xFFFFFFFFu, vy, o);
        vz += __shfl_xor_sync(0xFFFFFFFFu, vz, o);
    }
    if (lane == 0) {
        red[warp][0] = s;  red[warp][1] = vx;
        red[warp][2] = vy; red[warp][3] = vz;
    }
    __syncthreads();

    if (warp == 0 && lane < NWARPS) {
        s  = red[lane][0]; vx = red[lane][1];
        vy = red[lane][2]; vz = red[lane][3];
        #pragma unroll
        for (int o = 4; o > 0; o >>= 1) {
            s  += __shfl_xor_sync(0x000000FFu, s,  o);
            vx += __shfl_xor_sync(0x000000FFu, vx, o);
            vy += __shfl_xor_sync(0x000000FFu, vy, o);
            vz += __shfl_xor_sync(0x000000FFu, vz, o);
        }
        if (lane == 0)
            g_part[i * PARTS + part] = make_float4(s, vx, vy, vz);
    }
}

// one warp per row: fixed-order partial combine + magnitude + output
__global__ __launch_bounds__(NTHREADS)
void se3_finalize_kernel(const float* __restrict__ coords,
                         const float* __restrict__ nodef,
                         const float* __restrict__ w_mag,
                         const float* __restrict__ b_mag,
                         float* __restrict__ out)
{
    const int lane = threadIdx.x & 31;
    const int warp = threadIdx.x >> 5;
    const int row  = blockIdx.x * NWARPS + warp;

    float s = 0.f, vx = 0.f, vy = 0.f, vz = 0.f;
    if (lane < PARTS) {
        const float4 p = g_part[row * PARTS + lane];
        s = p.x; vx = p.y; vy = p.z; vz = p.w;
    }
    #pragma unroll
    for (int o = 1; o < PARTS; o <<= 1) {
        s  += __shfl_xor_sync(0xFFFFFFFFu, s,  o);
        vx += __shfl_xor_sync(0xFFFFFFFFu, vx, o);
        vy += __shfl_xor_sync(0xFFFFFFFFu, vy, o);
        vz += __shfl_xor_sync(0xFFFFFFFFu, vz, o);
    }

    // magnitude: tanh(node_features[row] @ w_mag + b_mag) * 0.1
    float a = fmaf(nodef[(size_t)row * NODE_DIM + lane],      __ldg(&w_mag[lane]),
              nodef[(size_t)row * NODE_DIM + 32 + lane] * __ldg(&w_mag[32 + lane]));
    #pragma unroll
    for (int o = 16; o > 0; o >>= 1) a += __shfl_xor_sync(0xFFFFFFFFu, a, o);

    if (lane == 0) {
        const float mag = tanhf(a + __ldg(&b_mag[0])) * 0.1f;
        const float fac = mag / s;
        out[3*row+0] = __ldg(&coords[3*row+0]) + vx * fac;
        out[3*row+1] = __ldg(&coords[3*row+1]) + vy * fac;
        out[3*row+2] = __ldg(&coords[3*row+2]) + vz * fac;
    }
}

extern "C" void kernel_launch(void* const* d_in, const int* in_sizes, int n_in,
                              void* d_out, int out_size)
{
    const float* coords = (const float*)d_in[0];
    const float* nodef  = (const float*)d_in[1];
    const float* pairf  = (const float*)d_in[2];
    const float* w_attn = (const float*)d_in[3];
    // d_in[4] = b_attn : softmax-invariant, unused
    const float* w_mag  = (const float*)d_in[5];
    const float* b_mag  = (const float*)d_in[6];
    float* out = (float*)d_out;

    dim3 grid_main(LL, PARTS);
    se3_main_kernel<<<grid_main, NTHREADS>>>(coords, pairf, w_attn);
    se3_finalize_kernel<<<LL / NWARPS, NTHREADS>>>(coords, nodef, w_mag, b_mag, out);
}